// round 4
// baseline (speedup 1.0000x reference)
#include <cuda_runtime.h>
#include <cuda_fp16.h>

#define N_NODES  100000
#define N_EDGES  600000
#define NODE_DIM 128
#define EDGE_DIM 16
#define OUT_DIM  128
#define EDGES_PER_WARP 20

// Scratch (fp16): Y[n][0:128] = x[n]@W_i + b, Y[n][128:256] = x[n]@W_j
__device__ __align__(16) __half g_Y[(size_t)N_NODES * 256];

// ---------------------------------------------------------------------------
// GEMM: Y[m0+.., n0+..] tile. BM=64 rows, BN=128 cols, 256 threads, 4x8 micro.
// grid.x = 2 (col halves: n0=0 -> W_i(+bias), n0=128 -> W_j), grid.y = 1563.
// Output converted to fp16.
// ---------------------------------------------------------------------------
__global__ void gemm_kernel(const float* __restrict__ x,
                            const float* __restrict__ W,
                            const float* __restrict__ b) {
    extern __shared__ float smem[];
    float* As = smem;               // [64][129] padded
    float* Ws = smem + 64 * 129;    // [128][128]

    const int n0  = blockIdx.x * 128;      // 0 or 128
    const int m0  = blockIdx.y * 64;
    const int tid = threadIdx.x;

    // Ws <- W rows [n0 .. n0+127], contiguous 64KB block.
    {
        const float4* Wsrc = (const float4*)(W + (size_t)n0 * 128);
        float4* Wd = (float4*)Ws;
        #pragma unroll
        for (int p = 0; p < 16; p++) Wd[tid + p * 256] = Wsrc[tid + p * 256];
    }
    // As <- x[m0 .. m0+63][0:128], zero-fill past N_NODES.
    {
        const float4* x4 = (const float4*)x;
        #pragma unroll
        for (int p = 0; p < 8; p++) {
            int idx = tid + p * 256;
            int row = idx >> 5;
            int c4  = idx & 31;
            float4 v = make_float4(0.f, 0.f, 0.f, 0.f);
            if (m0 + row < N_NODES) v = x4[(size_t)(m0 + row) * 32 + c4];
            float* dst = As + row * 129 + c4 * 4;
            dst[0] = v.x; dst[1] = v.y; dst[2] = v.z; dst[3] = v.w;
        }
    }
    __syncthreads();

    const int tx = tid & 15;     // col group: cols tx*4 and 64+tx*4
    const int ty = tid >> 4;     // row group: rows ty*4 .. +3

    float4 acc0[4], acc1[4];
    {
        const float4 zero = make_float4(0.f, 0.f, 0.f, 0.f);
        const float4* b4 = (const float4*)b;
        float4 i0 = (n0 == 0) ? b4[tx]      : zero;
        float4 i1 = (n0 == 0) ? b4[16 + tx] : zero;
        #pragma unroll
        for (int i = 0; i < 4; i++) { acc0[i] = i0; acc1[i] = i1; }
    }

    const float*  Ar  = As + (ty * 4) * 129;
    const float4* Ws4 = (const float4*)Ws;

    #pragma unroll 8
    for (int k = 0; k < 128; k++) {
        float a[4];
        a[0] = Ar[k];
        a[1] = Ar[129 + k];
        a[2] = Ar[258 + k];
        a[3] = Ar[387 + k];
        float4 w0 = Ws4[k * 32 + tx];
        float4 w1 = Ws4[k * 32 + 16 + tx];
        #pragma unroll
        for (int i = 0; i < 4; i++) {
            acc0[i].x += a[i] * w0.x; acc0[i].y += a[i] * w0.y;
            acc0[i].z += a[i] * w0.z; acc0[i].w += a[i] * w0.w;
            acc1[i].x += a[i] * w1.x; acc1[i].y += a[i] * w1.y;
            acc1[i].z += a[i] * w1.z; acc1[i].w += a[i] * w1.w;
        }
    }

    #pragma unroll
    for (int i = 0; i < 4; i++) {
        int row = m0 + ty * 4 + i;
        if (row < N_NODES) {
            // 4 floats -> 4 halfs (8 bytes) per store slot
            __half2 p0 = __floats2half2_rn(acc0[i].x, acc0[i].y);
            __half2 p1 = __floats2half2_rn(acc0[i].z, acc0[i].w);
            __half2 q0 = __floats2half2_rn(acc1[i].x, acc1[i].y);
            __half2 q1 = __floats2half2_rn(acc1[i].z, acc1[i].w);
            uint2 u0, u1;
            u0.x = *(unsigned*)&p0;  u0.y = *(unsigned*)&p1;
            u1.x = *(unsigned*)&q0;  u1.y = *(unsigned*)&q1;
            uint2* o = (uint2*)(g_Y + (size_t)row * 256 + n0);
            o[tx]      = u0;
            o[16 + tx] = u1;
        }
    }
}

// ---------------------------------------------------------------------------
// Edge kernel: 1 warp per 20 edges. Lane owns output dims [4*lane, 4*lane+4).
// W_e column slice held in registers (16 x float4), amortized over the edges.
// out[e] = Y[src][0:128] + Y[dst][128:256] + edge_attr[e] @ W_e
// ---------------------------------------------------------------------------
__global__ void __launch_bounds__(256)
edge_kernel(const int* __restrict__ ei,
            const float* __restrict__ edge_attr,
            const float* __restrict__ W,
            float* __restrict__ out) {
    const int lane = threadIdx.x & 31;
    const int warp = threadIdx.x >> 5;
    const int e0   = (blockIdx.x * 8 + warp) * EDGES_PER_WARP;

    // W_e slice for this lane's 4 output dims: rows k=0..15, cols 4*lane..+3
    float4 we[16];
    {
        const float* Wep = W + (size_t)256 * 128 + lane * 4;
        #pragma unroll
        for (int k = 0; k < 16; k++)
            we[k] = *(const float4*)(Wep + k * 128);
    }

    #pragma unroll 2
    for (int e = e0; e < e0 + EDGES_PER_WARP; e++) {
        const int s = ei[e];
        const int t = ei[N_EDGES + e];

        // fp16 gathers: 8 bytes per lane, coalesced 256B per warp
        uint2 ga = ((const uint2*)(g_Y + (size_t)s * 256))[lane];
        uint2 gb = ((const uint2*)(g_Y + (size_t)t * 256 + 128))[lane];

        float2 a0 = __half22float2(*(__half2*)&ga.x);
        float2 a1 = __half22float2(*(__half2*)&ga.y);
        float2 b0 = __half22float2(*(__half2*)&gb.x);
        float2 b1 = __half22float2(*(__half2*)&gb.y);

        float4 acc;
        acc.x = a0.x + b0.x;
        acc.y = a0.y + b0.y;
        acc.z = a1.x + b1.x;
        acc.w = a1.y + b1.y;

        const float4* ea4 = (const float4*)(edge_attr + (size_t)e * 16);
        #pragma unroll
        for (int q = 0; q < 4; q++) {
            float4 ev = ea4[q];   // uniform across warp -> L1 broadcast
            float4 w0 = we[4 * q + 0];
            float4 w1 = we[4 * q + 1];
            float4 w2 = we[4 * q + 2];
            float4 w3 = we[4 * q + 3];
            acc.x += ev.x * w0.x; acc.y += ev.x * w0.y; acc.z += ev.x * w0.z; acc.w += ev.x * w0.w;
            acc.x += ev.y * w1.x; acc.y += ev.y * w1.y; acc.z += ev.y * w1.z; acc.w += ev.y * w1.w;
            acc.x += ev.z * w2.x; acc.y += ev.z * w2.y; acc.z += ev.z * w2.z; acc.w += ev.z * w2.w;
            acc.x += ev.w * w3.x; acc.y += ev.w * w3.y; acc.z += ev.w * w3.z; acc.w += ev.w * w3.w;
        }

        ((float4*)(out + (size_t)e * 128))[lane] = acc;
    }
}

// ---------------------------------------------------------------------------
extern "C" void kernel_launch(void* const* d_in, const int* in_sizes, int n_in,
                              void* d_out, int out_size) {
    const float* x  = (const float*)d_in[0];
    const int*   ei = (const int*)d_in[1];
    const float* ea = (const float*)d_in[2];
    const float* W  = (const float*)d_in[3];
    const float* b  = (const float*)d_in[4];
    float* out = (float*)d_out;

    const size_t smem_bytes = (size_t)(64 * 129 + 128 * 128) * sizeof(float);
    cudaFuncSetAttribute(gemm_kernel,
                         cudaFuncAttributeMaxDynamicSharedMemorySize,
                         (int)smem_bytes);

    gemm_kernel<<<dim3(2, (N_NODES + 63) / 64), 256, smem_bytes>>>(x, W, b);
    // 3750 blocks * 8 warps * 20 edges = 600000
    edge_kernel<<<N_EDGES / (8 * EDGES_PER_WARP), 256>>>(ei, ea, W, out);
}

// round 5
// speedup vs baseline: 1.2881x; 1.2881x over previous
#include <cuda_runtime.h>
#include <cuda_fp16.h>

#define N_NODES  100000
#define N_EDGES  600000
#define NODE_DIM 128
#define EDGE_DIM 16
#define OUT_DIM  128
#define EPS 8   // edges per 64-thread stream

typedef unsigned long long ull;

// fma.rn.f32x2: packed 2xfp32 FMA (PTX-only; ptxas never auto-fuses)
#define FMA_F32X2(d, a, b, c) \
    asm("fma.rn.f32x2 %0, %1, %2, %3;" : "=l"(d) : "l"(a), "l"(b), "l"(c))
// pack {x, x} into one b64
#define PACK2(d, x) \
    asm("mov.b64 %0, {%1, %1};" : "=l"(d) : "f"(x))

union F4U { float4 f; ull u[2]; };
union F2U { float2 f; ull u; };

// Scratch (fp16): Y[n][0:128] = x[n]@W_i + b, Y[n][128:256] = x[n]@W_j
__device__ __align__(16) __half g_Y[(size_t)N_NODES * 256];

// ---------------------------------------------------------------------------
// GEMM: BM=64, BN=128, 256 threads, 4x8 microtile, f32x2 packed FMA.
// grid.x = 2 (n0=0 -> W_i + bias, n0=128 -> W_j), grid.y = 1563.
// ---------------------------------------------------------------------------
__global__ void gemm_kernel(const float* __restrict__ x,
                            const float* __restrict__ W,
                            const float* __restrict__ b) {
    extern __shared__ float smem[];
    float* As = smem;               // [64][129] padded
    float* Ws = smem + 64 * 129;    // [128][128]

    const int n0  = blockIdx.x * 128;
    const int m0  = blockIdx.y * 64;
    const int tid = threadIdx.x;

    {
        const float4* Wsrc = (const float4*)(W + (size_t)n0 * 128);
        float4* Wd = (float4*)Ws;
        #pragma unroll
        for (int p = 0; p < 16; p++) Wd[tid + p * 256] = Wsrc[tid + p * 256];
    }
    {
        const float4* x4 = (const float4*)x;
        #pragma unroll
        for (int p = 0; p < 8; p++) {
            int idx = tid + p * 256;
            int row = idx >> 5;
            int c4  = idx & 31;
            float4 v = make_float4(0.f, 0.f, 0.f, 0.f);
            if (m0 + row < N_NODES) v = x4[(size_t)(m0 + row) * 32 + c4];
            float* dst = As + row * 129 + c4 * 4;
            dst[0] = v.x; dst[1] = v.y; dst[2] = v.z; dst[3] = v.w;
        }
    }
    __syncthreads();

    const int tx = tid & 15;
    const int ty = tid >> 4;

    ull acc0[4][2], acc1[4][2];
    {
        F4U i0, i1;
        i0.f = make_float4(0.f, 0.f, 0.f, 0.f);
        i1.f = i0.f;
        if (n0 == 0) {
            const float4* b4 = (const float4*)b;
            i0.f = b4[tx];
            i1.f = b4[16 + tx];
        }
        #pragma unroll
        for (int i = 0; i < 4; i++) {
            acc0[i][0] = i0.u[0]; acc0[i][1] = i0.u[1];
            acc1[i][0] = i1.u[0]; acc1[i][1] = i1.u[1];
        }
    }

    const float* Ar = As + (ty * 4) * 129;
    const float4* Ws4 = (const float4*)Ws;

    #pragma unroll 4
    for (int k = 0; k < 128; k++) {
        ull pa[4];
        {
            float a0 = Ar[k];
            float a1 = Ar[129 + k];
            float a2 = Ar[258 + k];
            float a3 = Ar[387 + k];
            PACK2(pa[0], a0); PACK2(pa[1], a1);
            PACK2(pa[2], a2); PACK2(pa[3], a3);
        }
        F4U w0, w1;
        w0.f = Ws4[k * 32 + tx];
        w1.f = Ws4[k * 32 + 16 + tx];
        #pragma unroll
        for (int i = 0; i < 4; i++) {
            FMA_F32X2(acc0[i][0], pa[i], w0.u[0], acc0[i][0]);
            FMA_F32X2(acc0[i][1], pa[i], w0.u[1], acc0[i][1]);
            FMA_F32X2(acc1[i][0], pa[i], w1.u[0], acc1[i][0]);
            FMA_F32X2(acc1[i][1], pa[i], w1.u[1], acc1[i][1]);
        }
    }

    #pragma unroll
    for (int i = 0; i < 4; i++) {
        int row = m0 + ty * 4 + i;
        if (row < N_NODES) {
            F4U r0, r1;
            r0.u[0] = acc0[i][0]; r0.u[1] = acc0[i][1];
            r1.u[0] = acc1[i][0]; r1.u[1] = acc1[i][1];
            __half2 p0 = __floats2half2_rn(r0.f.x, r0.f.y);
            __half2 p1 = __floats2half2_rn(r0.f.z, r0.f.w);
            __half2 q0 = __floats2half2_rn(r1.f.x, r1.f.y);
            __half2 q1 = __floats2half2_rn(r1.f.z, r1.f.w);
            uint2 u0, u1;
            u0.x = *(unsigned*)&p0;  u0.y = *(unsigned*)&p1;
            u1.x = *(unsigned*)&q0;  u1.y = *(unsigned*)&q1;
            uint2* o = (uint2*)(g_Y + (size_t)row * 256 + n0);
            o[tx]      = u0;
            o[16 + tx] = u1;
        }
    }
}

// ---------------------------------------------------------------------------
// Edge kernel: 64-thread stream per edge, lane owns 2 output dims.
// W_e slice in 32 regs (16 x f32x2). One-edge lookahead on idx + gathers.
// ---------------------------------------------------------------------------
__global__ void __launch_bounds__(256)
edge_kernel(const int* __restrict__ ei,
            const float* __restrict__ edge_attr,
            const float* __restrict__ W,
            float* __restrict__ out) {
    const int tid    = threadIdx.x;
    const int lane2  = tid & 63;            // dim pair index 0..63
    const int stream = tid >> 6;            // 0..3
    const int e0     = (blockIdx.x * 4 + stream) * EPS;

    // W_e slice for dims {2*lane2, 2*lane2+1}, packed as f32x2
    ull we[16];
    {
        const float* Wep = W + (size_t)256 * 128 + 2 * lane2;
        #pragma unroll
        for (int k = 0; k < 16; k++)
            we[k] = *(const ull*)(Wep + k * 128);
    }

    // prefetch edge e0
    int s = ei[e0];
    int t = ei[N_EDGES + e0];
    unsigned ga = *(const unsigned*)(g_Y + (size_t)s * 256 + 2 * lane2);
    unsigned gb = *(const unsigned*)(g_Y + (size_t)t * 256 + 128 + 2 * lane2);

    #pragma unroll
    for (int i = 0; i < EPS; i++) {
        const int e = e0 + i;

        // lookahead: next edge's indices + gathers in flight during compute
        unsigned nga = 0, ngb = 0;
        if (i + 1 < EPS) {
            int ns = ei[e + 1];
            int nt = ei[N_EDGES + e + 1];
            nga = *(const unsigned*)(g_Y + (size_t)ns * 256 + 2 * lane2);
            ngb = *(const unsigned*)(g_Y + (size_t)nt * 256 + 128 + 2 * lane2);
        }

        // edge_attr: 16 floats, warp-uniform loads (L1 broadcast)
        float ea[16];
        {
            const float4* ea4 = (const float4*)(edge_attr + (size_t)e * 16);
            #pragma unroll
            for (int q = 0; q < 4; q++) {
                float4 v = ea4[q];
                ea[4 * q]     = v.x;
                ea[4 * q + 1] = v.y;
                ea[4 * q + 2] = v.z;
                ea[4 * q + 3] = v.w;
            }
        }

        float2 av = __half22float2(*(__half2*)&ga);
        float2 bv = __half22float2(*(__half2*)&gb);
        F2U acc;
        acc.f.x = av.x + bv.x;
        acc.f.y = av.y + bv.y;

        #pragma unroll
        for (int k = 0; k < 16; k++) {
            ull pe;
            PACK2(pe, ea[k]);
            FMA_F32X2(acc.u, pe, we[k], acc.u);
        }

        *(float2*)(out + (size_t)e * 128 + 2 * lane2) = acc.f;

        ga = nga;
        gb = ngb;
    }
}

// ---------------------------------------------------------------------------
extern "C" void kernel_launch(void* const* d_in, const int* in_sizes, int n_in,
                              void* d_out, int out_size) {
    const float* x  = (const float*)d_in[0];
    const int*   ei = (const int*)d_in[1];
    const float* ea = (const float*)d_in[2];
    const float* W  = (const float*)d_in[3];
    const float* b  = (const float*)d_in[4];
    float* out = (float*)d_out;

    const size_t smem_bytes = (size_t)(64 * 129 + 128 * 128) * sizeof(float);
    cudaFuncSetAttribute(gemm_kernel,
                         cudaFuncAttributeMaxDynamicSharedMemorySize,
                         (int)smem_bytes);

    gemm_kernel<<<dim3(2, (N_NODES + 63) / 64), 256, smem_bytes>>>(x, W, b);
    // 18750 blocks * 4 streams * 8 edges = 600000
    edge_kernel<<<N_EDGES / (4 * EPS), 256>>>(ei, ea, W, out);
}

// round 6
// speedup vs baseline: 1.9319x; 1.4999x over previous
#include <cuda_runtime.h>
#include <cuda_fp16.h>

#define N_NODES  100000
#define N_EDGES  600000
#define EPS 8   // edges per 64-thread stream

typedef unsigned long long ull;
typedef unsigned int u32;

// fma.rn.f32x2: packed 2xfp32 FMA (PTX-only)
#define FMA_F32X2(d, a, b, c) \
    asm("fma.rn.f32x2 %0, %1, %2, %3;" : "=l"(d) : "l"(a), "l"(b), "l"(c))
#define PACK2(d, x) \
    asm("mov.b64 %0, {%1, %1};" : "=l"(d) : "f"(x))

union F2U { float2 f; ull u; };

// Scratch (fp16): Y[n][0:128] = x[n]@W_i + b, Y[n][128:256] = x[n]@W_j
__device__ __align__(16) __half g_Y[(size_t)N_NODES * 256];
// W_i/W_j in fp16, transposed: g_Wt[h][n][k] = W[h*128 + k][n]
__device__ __align__(16) __half g_Wt[2 * 128 * 128];

// ---------------------------------------------------------------------------
__global__ void prep_Wt(const float* __restrict__ W) {
    int idx = blockIdx.x * 256 + threadIdx.x;   // 0..32767
    int h = idx >> 14, n = (idx >> 7) & 127, k = idx & 127;
    g_Wt[idx] = __float2half(W[((h << 7) + k) * 128 + n]);
}

// ---------------------------------------------------------------------------
__device__ __forceinline__ void ldsm_x4(u32 addr, u32& r0, u32& r1, u32& r2, u32& r3) {
    asm volatile("ldmatrix.sync.aligned.m8n8.x4.shared.b16 {%0,%1,%2,%3}, [%4];"
                 : "=r"(r0), "=r"(r1), "=r"(r2), "=r"(r3) : "r"(addr));
}
__device__ __forceinline__ void mma16816(float* c, const u32* a, u32 b0, u32 b1) {
    asm volatile("mma.sync.aligned.m16n8k16.row.col.f32.f16.f16.f32 "
                 "{%0,%1,%2,%3}, {%4,%5,%6,%7}, {%8,%9}, {%0,%1,%2,%3};"
                 : "+f"(c[0]), "+f"(c[1]), "+f"(c[2]), "+f"(c[3])
                 : "r"(a[0]), "r"(a[1]), "r"(a[2]), "r"(a[3]), "r"(b0), "r"(b1));
}

#define LDA 136  // halfs per smem row: 128 + 8 pad -> 272B stride, ldmatrix conflict-free

// BM=128, BN=128, K=128 single shot. grid = (2, 782). 8 warps: 4(m) x 2(n).
__global__ void __launch_bounds__(256) gemm_mma(const float* __restrict__ x,
                                                const float* __restrict__ b) {
    extern __shared__ __half sh[];
    __half* As = sh;               // [128][136]
    __half* Bs = sh + 128 * LDA;   // [128][136]

    const int tid = threadIdx.x;
    const int h   = blockIdx.x;          // 0: W_i (+bias), 1: W_j
    const int n0  = h << 7;
    const int m0  = blockIdx.y << 7;

    // Bs <- g_Wt[h] (straight 32KB copy, [n][k])
    {
        const uint4* src = (const uint4*)(g_Wt + h * 16384);
        #pragma unroll
        for (int p = 0; p < 8; p++) {
            int idx = tid + p * 256;         // uint4 units (8 halfs)
            int n = idx >> 4, c8 = idx & 15;
            *(uint4*)(Bs + n * LDA + c8 * 8) = src[idx];
        }
    }
    // As <- fp16(x[m0 .. m0+127][0:128]), zero past N_NODES
    {
        const float4* x4 = (const float4*)x;
        #pragma unroll
        for (int p = 0; p < 16; p++) {
            int idx = tid + p * 256;
            int row = idx >> 5, c4 = idx & 31;
            float4 v = make_float4(0.f, 0.f, 0.f, 0.f);
            if (m0 + row < N_NODES) v = x4[(size_t)(m0 + row) * 32 + c4];
            __half2 h0 = __floats2half2_rn(v.x, v.y);
            __half2 h1 = __floats2half2_rn(v.z, v.w);
            uint2 u; u.x = *(u32*)&h0; u.y = *(u32*)&h1;
            *(uint2*)(As + row * LDA + c4 * 4) = u;
        }
    }
    __syncthreads();

    const int lane   = tid & 31;
    const int wid    = tid >> 5;
    const int warp_m = wid >> 1;    // m offset 32*warp_m
    const int warp_n = wid & 1;     // n offset 64*warp_n

    float acc[2][8][4];
    #pragma unroll
    for (int mt = 0; mt < 2; mt++)
        #pragma unroll
        for (int nt = 0; nt < 8; nt++)
            #pragma unroll
            for (int i = 0; i < 4; i++) acc[mt][nt][i] = 0.f;

    const int lr = lane & 15;              // ldmatrix row within 16
    const int lc = (lane >> 4) << 3;       // ldmatrix col half-select (0/8)
    const u32 aBase = (u32)__cvta_generic_to_shared(As)
                      + ((warp_m * 32 + lr) * LDA + lc) * 2;
    const u32 bBase = (u32)__cvta_generic_to_shared(Bs)
                      + ((warp_n * 64 + lr) * LDA + lc) * 2;

    #pragma unroll
    for (int ks = 0; ks < 8; ks++) {       // k0 = ks*16 -> +32 bytes
        u32 a[2][4];
        ldsm_x4(aBase + ks * 32,                a[0][0], a[0][1], a[0][2], a[0][3]);
        ldsm_x4(aBase + 16 * LDA * 2 + ks * 32, a[1][0], a[1][1], a[1][2], a[1][3]);
        u32 br[4][4];
        #pragma unroll
        for (int q = 0; q < 4; q++)
            ldsm_x4(bBase + q * 16 * LDA * 2 + ks * 32,
                    br[q][0], br[q][1], br[q][2], br[q][3]);
        #pragma unroll
        for (int mt = 0; mt < 2; mt++)
            #pragma unroll
            for (int q = 0; q < 4; q++) {
                mma16816(acc[mt][2 * q],     a[mt], br[q][0], br[q][2]);
                mma16816(acc[mt][2 * q + 1], a[mt], br[q][1], br[q][3]);
            }
    }

    // Epilogue: (+bias for h==0), fp16 store to g_Y
    const int gr = lane >> 2;
    const int gc = (lane & 3) * 2;
    #pragma unroll
    for (int mt = 0; mt < 2; mt++) {
        int r0 = m0 + warp_m * 32 + mt * 16 + gr;
        #pragma unroll
        for (int nt = 0; nt < 8; nt++) {
            int cb = warp_n * 64 + nt * 8 + gc;     // 0..127
            float b0 = 0.f, b1 = 0.f;
            if (h == 0) { b0 = b[cb]; b1 = b[cb + 1]; }
            if (r0 < N_NODES) {
                __half2 v = __floats2half2_rn(acc[mt][nt][0] + b0,
                                              acc[mt][nt][1] + b1);
                *(__half2*)(g_Y + (size_t)r0 * 256 + n0 + cb) = v;
            }
            if (r0 + 8 < N_NODES) {
                __half2 v = __floats2half2_rn(acc[mt][nt][2] + b0,
                                              acc[mt][nt][3] + b1);
                *(__half2*)(g_Y + (size_t)(r0 + 8) * 256 + n0 + cb) = v;
            }
        }
    }
}

// ---------------------------------------------------------------------------
// Edge kernel (unchanged from R5): 64-thread stream per edge, 2 dims/lane,
// W_e slice in 32 regs, 1-edge lookahead.
// ---------------------------------------------------------------------------
__global__ void __launch_bounds__(256)
edge_kernel(const int* __restrict__ ei,
            const float* __restrict__ edge_attr,
            const float* __restrict__ W,
            float* __restrict__ out) {
    const int tid    = threadIdx.x;
    const int lane2  = tid & 63;
    const int stream = tid >> 6;
    const int e0     = (blockIdx.x * 4 + stream) * EPS;

    ull we[16];
    {
        const float* Wep = W + (size_t)256 * 128 + 2 * lane2;
        #pragma unroll
        for (int k = 0; k < 16; k++)
            we[k] = *(const ull*)(Wep + k * 128);
    }

    int s = ei[e0];
    int t = ei[N_EDGES + e0];
    unsigned ga = *(const unsigned*)(g_Y + (size_t)s * 256 + 2 * lane2);
    unsigned gb = *(const unsigned*)(g_Y + (size_t)t * 256 + 128 + 2 * lane2);

    #pragma unroll
    for (int i = 0; i < EPS; i++) {
        const int e = e0 + i;

        unsigned nga = 0, ngb = 0;
        if (i + 1 < EPS) {
            int ns = ei[e + 1];
            int nt = ei[N_EDGES + e + 1];
            nga = *(const unsigned*)(g_Y + (size_t)ns * 256 + 2 * lane2);
            ngb = *(const unsigned*)(g_Y + (size_t)nt * 256 + 128 + 2 * lane2);
        }

        float ea[16];
        {
            const float4* ea4 = (const float4*)(edge_attr + (size_t)e * 16);
            #pragma unroll
            for (int q = 0; q < 4; q++) {
                float4 v = ea4[q];
                ea[4 * q]     = v.x;
                ea[4 * q + 1] = v.y;
                ea[4 * q + 2] = v.z;
                ea[4 * q + 3] = v.w;
            }
        }

        float2 av = __half22float2(*(__half2*)&ga);
        float2 bv = __half22float2(*(__half2*)&gb);
        F2U acc;
        acc.f.x = av.x + bv.x;
        acc.f.y = av.y + bv.y;

        #pragma unroll
        for (int k = 0; k < 16; k++) {
            ull pe;
            PACK2(pe, ea[k]);
            FMA_F32X2(acc.u, pe, we[k], acc.u);
        }

        *(float2*)(out + (size_t)e * 128 + 2 * lane2) = acc.f;

        ga = nga;
        gb = ngb;
    }
}

// ---------------------------------------------------------------------------
extern "C" void kernel_launch(void* const* d_in, const int* in_sizes, int n_in,
                              void* d_out, int out_size) {
    const float* x  = (const float*)d_in[0];
    const int*   ei = (const int*)d_in[1];
    const float* ea = (const float*)d_in[2];
    const float* W  = (const float*)d_in[3];
    const float* b  = (const float*)d_in[4];
    float* out = (float*)d_out;

    const int smem_bytes = 2 * 128 * LDA * (int)sizeof(__half);   // 69632
    cudaFuncSetAttribute(gemm_mma,
                         cudaFuncAttributeMaxDynamicSharedMemorySize, smem_bytes);

    prep_Wt<<<128, 256>>>(W);
    gemm_mma<<<dim3(2, (N_NODES + 127) / 128), 256, smem_bytes>>>(x, b);
    edge_kernel<<<N_EDGES / (4 * EPS), 256>>>(ei, ea, W, out);
}

// round 7
// speedup vs baseline: 2.3550x; 1.2190x over previous
#include <cuda_runtime.h>
#include <cuda_fp16.h>

#define N_NODES  100000
#define N_EDGES  600000

typedef unsigned long long ull;
typedef unsigned int u32;

// Scratch (fp16): Y[n][0:128] = x[n]@W_i + b, Y[n][128:256] = x[n]@W_j
__device__ __align__(16) __half g_Y[(size_t)N_NODES * 256];
// W_i/W_j in fp16, transposed: g_Wt[h][n][k] = W[h*128 + k][n]
__device__ __align__(16) __half g_Wt[2 * 128 * 128];
// W_e in fp16, transposed: g_Wet[n][k] = W[256 + k][n]  (128 x 16)
__device__ __align__(16) __half g_Wet[128 * 16];

// ---------------------------------------------------------------------------
__global__ void prep_Wt(const float* __restrict__ W) {
    int idx = blockIdx.x * 256 + threadIdx.x;   // 0..32767
    int h = idx >> 14, n = (idx >> 7) & 127, k = idx & 127;
    g_Wt[idx] = __float2half(W[((h << 7) + k) * 128 + n]);
}
__global__ void prep_We(const float* __restrict__ W) {
    int idx = blockIdx.x * 256 + threadIdx.x;   // 0..2047
    int n = idx >> 4, k = idx & 15;
    g_Wet[idx] = __float2half(W[(256 + k) * 128 + n]);
}

// ---------------------------------------------------------------------------
__device__ __forceinline__ void ldsm_x4(u32 addr, u32& r0, u32& r1, u32& r2, u32& r3) {
    asm volatile("ldmatrix.sync.aligned.m8n8.x4.shared.b16 {%0,%1,%2,%3}, [%4];"
                 : "=r"(r0), "=r"(r1), "=r"(r2), "=r"(r3) : "r"(addr));
}
__device__ __forceinline__ void mma16816(float* c, const u32* a, u32 b0, u32 b1) {
    asm volatile("mma.sync.aligned.m16n8k16.row.col.f32.f16.f16.f32 "
                 "{%0,%1,%2,%3}, {%4,%5,%6,%7}, {%8,%9}, {%0,%1,%2,%3};"
                 : "+f"(c[0]), "+f"(c[1]), "+f"(c[2]), "+f"(c[3])
                 : "r"(a[0]), "r"(a[1]), "r"(a[2]), "r"(a[3]), "r"(b0), "r"(b1));
}

#define LDA 136  // node-GEMM smem stride (halfs)

// ---------------------------------------------------------------------------
// Node GEMM (unchanged from R6): BM=128, BN=128, K=128. grid = (2, 782).
// ---------------------------------------------------------------------------
__global__ void __launch_bounds__(256) gemm_mma(const float* __restrict__ x,
                                                const float* __restrict__ b) {
    extern __shared__ __half sh[];
    __half* As = sh;               // [128][136]
    __half* Bs = sh + 128 * LDA;   // [128][136]

    const int tid = threadIdx.x;
    const int h   = blockIdx.x;
    const int n0  = h << 7;
    const int m0  = blockIdx.y << 7;

    {
        const uint4* src = (const uint4*)(g_Wt + h * 16384);
        #pragma unroll
        for (int p = 0; p < 8; p++) {
            int idx = tid + p * 256;
            int n = idx >> 4, c8 = idx & 15;
            *(uint4*)(Bs + n * LDA + c8 * 8) = src[idx];
        }
    }
    {
        const float4* x4 = (const float4*)x;
        #pragma unroll
        for (int p = 0; p < 16; p++) {
            int idx = tid + p * 256;
            int row = idx >> 5, c4 = idx & 31;
            float4 v = make_float4(0.f, 0.f, 0.f, 0.f);
            if (m0 + row < N_NODES) v = x4[(size_t)(m0 + row) * 32 + c4];
            __half2 h0 = __floats2half2_rn(v.x, v.y);
            __half2 h1 = __floats2half2_rn(v.z, v.w);
            uint2 u; u.x = *(u32*)&h0; u.y = *(u32*)&h1;
            *(uint2*)(As + row * LDA + c4 * 4) = u;
        }
    }
    __syncthreads();

    const int lane   = tid & 31;
    const int wid    = tid >> 5;
    const int warp_m = wid >> 1;
    const int warp_n = wid & 1;

    float acc[2][8][4];
    #pragma unroll
    for (int mt = 0; mt < 2; mt++)
        #pragma unroll
        for (int nt = 0; nt < 8; nt++)
            #pragma unroll
            for (int i = 0; i < 4; i++) acc[mt][nt][i] = 0.f;

    const int lr = lane & 15;
    const int lc = (lane >> 4) << 3;
    const u32 aBase = (u32)__cvta_generic_to_shared(As)
                      + ((warp_m * 32 + lr) * LDA + lc) * 2;
    const u32 bBase = (u32)__cvta_generic_to_shared(Bs)
                      + ((warp_n * 64 + lr) * LDA + lc) * 2;

    #pragma unroll
    for (int ks = 0; ks < 8; ks++) {
        u32 a[2][4];
        ldsm_x4(aBase + ks * 32,                a[0][0], a[0][1], a[0][2], a[0][3]);
        ldsm_x4(aBase + 16 * LDA * 2 + ks * 32, a[1][0], a[1][1], a[1][2], a[1][3]);
        u32 br[4][4];
        #pragma unroll
        for (int q = 0; q < 4; q++)
            ldsm_x4(bBase + q * 16 * LDA * 2 + ks * 32,
                    br[q][0], br[q][1], br[q][2], br[q][3]);
        #pragma unroll
        for (int mt = 0; mt < 2; mt++)
            #pragma unroll
            for (int q = 0; q < 4; q++) {
                mma16816(acc[mt][2 * q],     a[mt], br[q][0], br[q][2]);
                mma16816(acc[mt][2 * q + 1], a[mt], br[q][1], br[q][3]);
            }
    }

    const int gr = lane >> 2;
    const int gc = (lane & 3) * 2;
    #pragma unroll
    for (int mt = 0; mt < 2; mt++) {
        int r0 = m0 + warp_m * 32 + mt * 16 + gr;
        #pragma unroll
        for (int nt = 0; nt < 8; nt++) {
            int cb = warp_n * 64 + nt * 8 + gc;
            float b0 = 0.f, b1 = 0.f;
            if (h == 0) { b0 = b[cb]; b1 = b[cb + 1]; }
            if (r0 < N_NODES) {
                __half2 v = __floats2half2_rn(acc[mt][nt][0] + b0,
                                              acc[mt][nt][1] + b1);
                *(__half2*)(g_Y + (size_t)r0 * 256 + n0 + cb) = v;
            }
            if (r0 + 8 < N_NODES) {
                __half2 v = __floats2half2_rn(acc[mt][nt][2] + b0,
                                              acc[mt][nt][3] + b1);
                *(__half2*)(g_Y + (size_t)(r0 + 8) * 256 + n0 + cb) = v;
            }
        }
    }
}

// ---------------------------------------------------------------------------
// Fused edge kernel: 128 edges per block.
//   MMA: sAcc[e][:] = edge_attr[e] @ W_e  (fp16 in, fp32 accum, one k-step)
//   Epilogue: warp per edge, lane owns 4 dims; coalesced fp16 gathers of
//   Y[src] / Y[dst], add staged acc, STG.128 out. 1-edge lookahead.
// ---------------------------------------------------------------------------
#define EW 24   // edge smem tile stride in halfs (48B: conflict-free ldmatrix)

__global__ void __launch_bounds__(256)
edge_fused(const int* __restrict__ ei,
           const float* __restrict__ edge_attr,
           float* __restrict__ out) {
    extern __shared__ float smem_f[];
    float*  sAcc = smem_f;                              // [128][132] fp32
    __half* sEA  = (__half*)(smem_f + 128 * 132);       // [128][EW]
    __half* sWe  = sEA + 128 * EW;                      // [128][EW]
    int*    sIdx = (int*)(sWe + 128 * EW);              // [256]

    const int tid = threadIdx.x;
    const int e0  = blockIdx.x * 128;

    // W_e^T tile: 2048 halfs, one uint4 per thread
    {
        int n = tid >> 1, part = tid & 1;
        *(uint4*)(sWe + n * EW + part * 8) = ((const uint4*)g_Wet)[tid];
    }
    // edge_attr tile -> fp16, zero-pad past N_EDGES
    {
        #pragma unroll
        for (int p = 0; p < 2; p++) {
            int idx = tid + p * 256;          // 0..511
            int row = idx >> 2, q = idx & 3;
            float4 v = make_float4(0.f, 0.f, 0.f, 0.f);
            if (e0 + row < N_EDGES)
                v = ((const float4*)edge_attr)[(size_t)(e0 + row) * 4 + q];
            __half2 h0 = __floats2half2_rn(v.x, v.y);
            __half2 h1 = __floats2half2_rn(v.z, v.w);
            uint2 u; u.x = *(u32*)&h0; u.y = *(u32*)&h1;
            *(uint2*)(sEA + row * EW + q * 4) = u;
        }
    }
    // indices
    {
        int row = tid & 127;
        int src_side = tid >> 7;              // 0: src, 1: dst
        int v = 0;
        if (e0 + row < N_EDGES)
            v = ei[(size_t)src_side * N_EDGES + e0 + row];
        sIdx[src_side * 128 + row] = v;
    }
    __syncthreads();

    // ---- MMA: one m16n8k16 k-step ----
    const int lane   = tid & 31;
    const int wid    = tid >> 5;
    const int warp_m = wid >> 1;
    const int warp_n = wid & 1;

    float acc[2][8][4];
    #pragma unroll
    for (int mt = 0; mt < 2; mt++)
        #pragma unroll
        for (int nt = 0; nt < 8; nt++)
            #pragma unroll
            for (int i = 0; i < 4; i++) acc[mt][nt][i] = 0.f;

    {
        const int lr = lane & 15;
        const int lc = (lane >> 4) << 3;
        const u32 aBase = (u32)__cvta_generic_to_shared(sEA)
                          + ((warp_m * 32 + lr) * EW + lc) * 2;
        const u32 bBase = (u32)__cvta_generic_to_shared(sWe)
                          + ((warp_n * 64 + lr) * EW + lc) * 2;
        u32 a[2][4];
        ldsm_x4(aBase,               a[0][0], a[0][1], a[0][2], a[0][3]);
        ldsm_x4(aBase + 16 * EW * 2, a[1][0], a[1][1], a[1][2], a[1][3]);
        u32 br[4][4];
        #pragma unroll
        for (int q = 0; q < 4; q++)
            ldsm_x4(bBase + q * 16 * EW * 2,
                    br[q][0], br[q][1], br[q][2], br[q][3]);
        #pragma unroll
        for (int mt = 0; mt < 2; mt++)
            #pragma unroll
            for (int q = 0; q < 4; q++) {
                mma16816(acc[mt][2 * q],     a[mt], br[q][0], br[q][2]);
                mma16816(acc[mt][2 * q + 1], a[mt], br[q][1], br[q][3]);
            }
    }

    // stage acc -> smem
    {
        const int gr = lane >> 2;
        const int gc = (lane & 3) * 2;
        #pragma unroll
        for (int mt = 0; mt < 2; mt++) {
            int r0 = warp_m * 32 + mt * 16 + gr;
            #pragma unroll
            for (int nt = 0; nt < 8; nt++) {
                int cb = warp_n * 64 + nt * 8 + gc;
                *(float2*)(sAcc + r0 * 132 + cb) =
                    make_float2(acc[mt][nt][0], acc[mt][nt][1]);
                *(float2*)(sAcc + (r0 + 8) * 132 + cb) =
                    make_float2(acc[mt][nt][2], acc[mt][nt][3]);
            }
        }
    }
    __syncthreads();

    // ---- Epilogue: warp per edge, 16 edges per warp, 1-edge lookahead ----
    {
        int row = wid * 16;
        int s = sIdx[row];
        int t = sIdx[128 + row];
        uint2 ga = *(const uint2*)(g_Y + (size_t)s * 256 + lane * 4);
        uint2 gb = *(const uint2*)(g_Y + (size_t)t * 256 + 128 + lane * 4);

        #pragma unroll
        for (int i = 0; i < 16; i++) {
            int r = wid * 16 + i;
            int e = e0 + r;

            uint2 nga = ga, ngb = gb;
            if (i + 1 < 16) {
                int ns = sIdx[r + 1];
                int nt = sIdx[128 + r + 1];
                nga = *(const uint2*)(g_Y + (size_t)ns * 256 + lane * 4);
                ngb = *(const uint2*)(g_Y + (size_t)nt * 256 + 128 + lane * 4);
            }

            if (e < N_EDGES) {
                float4 ac = *(const float4*)(sAcc + r * 132 + lane * 4);
                float2 a0 = __half22float2(*(__half2*)&ga.x);
                float2 a1 = __half22float2(*(__half2*)&ga.y);
                float2 b0 = __half22float2(*(__half2*)&gb.x);
                float2 b1 = __half22float2(*(__half2*)&gb.y);
                float4 r4;
                r4.x = ac.x + a0.x + b0.x;
                r4.y = ac.y + a0.y + b0.y;
                r4.z = ac.z + a1.x + b1.x;
                r4.w = ac.w + a1.y + b1.y;
                *(float4*)(out + (size_t)e * 128 + lane * 4) = r4;
            }
            ga = nga;
            gb = ngb;
        }
    }
}

// ---------------------------------------------------------------------------
extern "C" void kernel_launch(void* const* d_in, const int* in_sizes, int n_in,
                              void* d_out, int out_size) {
    const float* x  = (const float*)d_in[0];
    const int*   ei = (const int*)d_in[1];
    const float* ea = (const float*)d_in[2];
    const float* W  = (const float*)d_in[3];
    const float* b  = (const float*)d_in[4];
    float* out = (float*)d_out;

    const int gemm_smem = 2 * 128 * LDA * (int)sizeof(__half);     // 69632
    cudaFuncSetAttribute(gemm_mma,
                         cudaFuncAttributeMaxDynamicSharedMemorySize, gemm_smem);
    const int edge_smem = 128 * 132 * 4 + 2 * 128 * EW * 2 + 256 * 4;  // 80896
    cudaFuncSetAttribute(edge_fused,
                         cudaFuncAttributeMaxDynamicSharedMemorySize, edge_smem);

    prep_Wt<<<128, 256>>>(W);
    prep_We<<<8, 256>>>(W);
    gemm_mma<<<dim3(2, (N_NODES + 127) / 128), 256, gemm_smem>>>(x, b);
    edge_fused<<<(N_EDGES + 127) / 128, 256, edge_smem>>>(ei, ea, out);
}

// round 8
// speedup vs baseline: 3.1742x; 1.3478x over previous
#include <cuda_runtime.h>
#include <cuda_fp16.h>

#define N_NODES  100000
#define N_EDGES  600000

typedef unsigned long long ull;
typedef unsigned int u32;

// Scratch (fp16): Y[n][0:128] = x[n]@W_i + b, Y[n][128:256] = x[n]@W_j
__device__ __align__(16) __half g_Y[(size_t)N_NODES * 256];
// W_i/W_j in fp16, transposed: g_Wt[h][n][k] = W[h*128 + k][n]
__device__ __align__(16) __half g_Wt[2 * 128 * 128];
// W_e in fp16, transposed: g_Wet[n][k] = W[256 + k][n]  (128 x 16)
__device__ __align__(16) __half g_Wet[128 * 16];

// ---------------------------------------------------------------------------
__global__ void prep_Wt(const float* __restrict__ W) {
    int idx = blockIdx.x * 256 + threadIdx.x;   // 0..32767
    int h = idx >> 14, n = (idx >> 7) & 127, k = idx & 127;
    g_Wt[idx] = __float2half(W[((h << 7) + k) * 128 + n]);
}
__global__ void prep_We(const float* __restrict__ W) {
    int idx = blockIdx.x * 256 + threadIdx.x;   // 0..2047
    int n = idx >> 4, k = idx & 15;
    g_Wet[idx] = __float2half(W[(256 + k) * 128 + n]);
}

// ---------------------------------------------------------------------------
__device__ __forceinline__ void ldsm_x4(u32 addr, u32& r0, u32& r1, u32& r2, u32& r3) {
    asm volatile("ldmatrix.sync.aligned.m8n8.x4.shared.b16 {%0,%1,%2,%3}, [%4];"
                 : "=r"(r0), "=r"(r1), "=r"(r2), "=r"(r3) : "r"(addr));
}
__device__ __forceinline__ void mma16816(float* c, const u32* a, u32 b0, u32 b1) {
    asm volatile("mma.sync.aligned.m16n8k16.row.col.f32.f16.f16.f32 "
                 "{%0,%1,%2,%3}, {%4,%5,%6,%7}, {%8,%9}, {%0,%1,%2,%3};"
                 : "+f"(c[0]), "+f"(c[1]), "+f"(c[2]), "+f"(c[3])
                 : "r"(a[0]), "r"(a[1]), "r"(a[2]), "r"(a[3]), "r"(b0), "r"(b1));
}

#define LDA 136  // node-GEMM smem stride (halfs)

// ---------------------------------------------------------------------------
// Node GEMM (unchanged): BM=128, BN=128, K=128. grid = (2, 782).
// ---------------------------------------------------------------------------
__global__ void __launch_bounds__(256) gemm_mma(const float* __restrict__ x,
                                                const float* __restrict__ b) {
    extern __shared__ __half sh[];
    __half* As = sh;               // [128][136]
    __half* Bs = sh + 128 * LDA;   // [128][136]

    const int tid = threadIdx.x;
    const int h   = blockIdx.x;
    const int n0  = h << 7;
    const int m0  = blockIdx.y << 7;

    {
        const uint4* src = (const uint4*)(g_Wt + h * 16384);
        #pragma unroll
        for (int p = 0; p < 8; p++) {
            int idx = tid + p * 256;
            int n = idx >> 4, c8 = idx & 15;
            *(uint4*)(Bs + n * LDA + c8 * 8) = src[idx];
        }
    }
    {
        const float4* x4 = (const float4*)x;
        #pragma unroll
        for (int p = 0; p < 16; p++) {
            int idx = tid + p * 256;
            int row = idx >> 5, c4 = idx & 31;
            float4 v = make_float4(0.f, 0.f, 0.f, 0.f);
            if (m0 + row < N_NODES) v = x4[(size_t)(m0 + row) * 32 + c4];
            __half2 h0 = __floats2half2_rn(v.x, v.y);
            __half2 h1 = __floats2half2_rn(v.z, v.w);
            uint2 u; u.x = *(u32*)&h0; u.y = *(u32*)&h1;
            *(uint2*)(As + row * LDA + c4 * 4) = u;
        }
    }
    __syncthreads();

    const int lane   = tid & 31;
    const int wid    = tid >> 5;
    const int warp_m = wid >> 1;
    const int warp_n = wid & 1;

    float acc[2][8][4];
    #pragma unroll
    for (int mt = 0; mt < 2; mt++)
        #pragma unroll
        for (int nt = 0; nt < 8; nt++)
            #pragma unroll
            for (int i = 0; i < 4; i++) acc[mt][nt][i] = 0.f;

    const int lr = lane & 15;
    const int lc = (lane >> 4) << 3;
    const u32 aBase = (u32)__cvta_generic_to_shared(As)
                      + ((warp_m * 32 + lr) * LDA + lc) * 2;
    const u32 bBase = (u32)__cvta_generic_to_shared(Bs)
                      + ((warp_n * 64 + lr) * LDA + lc) * 2;

    #pragma unroll
    for (int ks = 0; ks < 8; ks++) {
        u32 a[2][4];
        ldsm_x4(aBase + ks * 32,                a[0][0], a[0][1], a[0][2], a[0][3]);
        ldsm_x4(aBase + 16 * LDA * 2 + ks * 32, a[1][0], a[1][1], a[1][2], a[1][3]);
        u32 br[4][4];
        #pragma unroll
        for (int q = 0; q < 4; q++)
            ldsm_x4(bBase + q * 16 * LDA * 2 + ks * 32,
                    br[q][0], br[q][1], br[q][2], br[q][3]);
        #pragma unroll
        for (int mt = 0; mt < 2; mt++)
            #pragma unroll
            for (int q = 0; q < 4; q++) {
                mma16816(acc[mt][2 * q],     a[mt], br[q][0], br[q][2]);
                mma16816(acc[mt][2 * q + 1], a[mt], br[q][1], br[q][3]);
            }
    }

    const int gr = lane >> 2;
    const int gc = (lane & 3) * 2;
    #pragma unroll
    for (int mt = 0; mt < 2; mt++) {
        int r0 = m0 + warp_m * 32 + mt * 16 + gr;
        #pragma unroll
        for (int nt = 0; nt < 8; nt++) {
            int cb = warp_n * 64 + nt * 8 + gc;
            float b0 = 0.f, b1 = 0.f;
            if (h == 0) { b0 = b[cb]; b1 = b[cb + 1]; }
            if (r0 < N_NODES) {
                __half2 v = __floats2half2_rn(acc[mt][nt][0] + b0,
                                              acc[mt][nt][1] + b1);
                *(__half2*)(g_Y + (size_t)r0 * 256 + n0 + cb) = v;
            }
            if (r0 + 8 < N_NODES) {
                __half2 v = __floats2half2_rn(acc[mt][nt][2] + b0,
                                              acc[mt][nt][3] + b1);
                *(__half2*)(g_Y + (size_t)(r0 + 8) * 256 + n0 + cb) = v;
            }
        }
    }
}

// ---------------------------------------------------------------------------
// Fused edge kernel: 128 edges per block.
//   MMA (one k-step): ea @ W_e -> sAcc (fp16, 33KB -> 4 blocks/SM).
//   Epilogue: warp per edge, lane owns 4 dims, depth-2 gather pipeline;
//   first two gathers issued BEFORE the MMA so they hide under it.
// ---------------------------------------------------------------------------
#define EW  24   // edge_attr / W_e smem stride (halfs)
#define SAW 132  // sAcc stride (halfs)

__global__ void __launch_bounds__(256)
edge_fused(const int* __restrict__ ei,
           const float* __restrict__ edge_attr,
           float* __restrict__ out) {
    extern __shared__ __half smem_h[];
    __half* sAcc = smem_h;                        // [128][132] fp16
    __half* sEA  = sAcc + 128 * SAW;              // [128][EW]
    __half* sWe  = sEA + 128 * EW;                // [128][EW]
    int*    sIdx = (int*)(sWe + 128 * EW);        // [256]

    const int tid = threadIdx.x;
    const int e0  = blockIdx.x * 128;

    // W_e^T tile
    {
        int n = tid >> 1, part = tid & 1;
        *(uint4*)(sWe + n * EW + part * 8) = ((const uint4*)g_Wet)[tid];
    }
    // edge_attr tile -> fp16, zero-pad past N_EDGES
    {
        #pragma unroll
        for (int p = 0; p < 2; p++) {
            int idx = tid + p * 256;
            int row = idx >> 2, q = idx & 3;
            float4 v = make_float4(0.f, 0.f, 0.f, 0.f);
            if (e0 + row < N_EDGES)
                v = ((const float4*)edge_attr)[(size_t)(e0 + row) * 4 + q];
            __half2 h0 = __floats2half2_rn(v.x, v.y);
            __half2 h1 = __floats2half2_rn(v.z, v.w);
            uint2 u; u.x = *(u32*)&h0; u.y = *(u32*)&h1;
            *(uint2*)(sEA + row * EW + q * 4) = u;
        }
    }
    // indices
    {
        int row = tid & 127;
        int side = tid >> 7;
        int v = 0;
        if (e0 + row < N_EDGES) v = ei[(size_t)side * N_EDGES + e0 + row];
        sIdx[side * 128 + row] = v;
    }
    __syncthreads();

    const int lane   = tid & 31;
    const int wid    = tid >> 5;
    const int warp_m = wid >> 1;
    const int warp_n = wid & 1;
    const int row0   = wid * 16;    // this warp's first edge row

    // --- prefetch gathers for edges row0, row0+1 (fly during MMA) ---
    uint2 ga[2], gb[2];
    {
        int s0 = sIdx[row0],     t0 = sIdx[128 + row0];
        int s1 = sIdx[row0 + 1], t1 = sIdx[128 + row0 + 1];
        ga[0] = *(const uint2*)(g_Y + (size_t)s0 * 256 + lane * 4);
        gb[0] = *(const uint2*)(g_Y + (size_t)t0 * 256 + 128 + lane * 4);
        ga[1] = *(const uint2*)(g_Y + (size_t)s1 * 256 + lane * 4);
        gb[1] = *(const uint2*)(g_Y + (size_t)t1 * 256 + 128 + lane * 4);
    }

    // ---- MMA: one m16n8k16 k-step ----
    float acc[2][8][4];
    #pragma unroll
    for (int mt = 0; mt < 2; mt++)
        #pragma unroll
        for (int nt = 0; nt < 8; nt++)
            #pragma unroll
            for (int i = 0; i < 4; i++) acc[mt][nt][i] = 0.f;

    {
        const int lr = lane & 15;
        const int lc = (lane >> 4) << 3;
        const u32 aBase = (u32)__cvta_generic_to_shared(sEA)
                          + ((warp_m * 32 + lr) * EW + lc) * 2;
        const u32 bBase = (u32)__cvta_generic_to_shared(sWe)
                          + ((warp_n * 64 + lr) * EW + lc) * 2;
        u32 a[2][4];
        ldsm_x4(aBase,               a[0][0], a[0][1], a[0][2], a[0][3]);
        ldsm_x4(aBase + 16 * EW * 2, a[1][0], a[1][1], a[1][2], a[1][3]);
        u32 br[4][4];
        #pragma unroll
        for (int q = 0; q < 4; q++)
            ldsm_x4(bBase + q * 16 * EW * 2,
                    br[q][0], br[q][1], br[q][2], br[q][3]);
        #pragma unroll
        for (int mt = 0; mt < 2; mt++)
            #pragma unroll
            for (int q = 0; q < 4; q++) {
                mma16816(acc[mt][2 * q],     a[mt], br[q][0], br[q][2]);
                mma16816(acc[mt][2 * q + 1], a[mt], br[q][1], br[q][3]);
            }
    }

    // stage acc -> smem (fp16)
    {
        const int gr = lane >> 2;
        const int gc = (lane & 3) * 2;
        #pragma unroll
        for (int mt = 0; mt < 2; mt++) {
            int r0 = warp_m * 32 + mt * 16 + gr;
            #pragma unroll
            for (int nt = 0; nt < 8; nt++) {
                int cb = warp_n * 64 + nt * 8 + gc;
                __half2 v0 = __floats2half2_rn(acc[mt][nt][0], acc[mt][nt][1]);
                __half2 v1 = __floats2half2_rn(acc[mt][nt][2], acc[mt][nt][3]);
                *(__half2*)(sAcc + r0 * SAW + cb) = v0;
                *(__half2*)(sAcc + (r0 + 8) * SAW + cb) = v1;
            }
        }
    }
    __syncthreads();

    // ---- Epilogue: 16 edges per warp, depth-2 pipeline ----
    #pragma unroll
    for (int i = 0; i < 16; i++) {
        int r = row0 + i;
        int e = e0 + r;

        // prefetch edge i+2
        uint2 nga, ngb;
        if (i + 2 < 16) {
            int ns = sIdx[r + 2];
            int nt = sIdx[128 + r + 2];
            nga = *(const uint2*)(g_Y + (size_t)ns * 256 + lane * 4);
            ngb = *(const uint2*)(g_Y + (size_t)nt * 256 + 128 + lane * 4);
        } else {
            nga = ga[i & 1]; ngb = gb[i & 1];
        }

        if (e < N_EDGES) {
            uint2 ua = ga[i & 1], ub = gb[i & 1];
            uint2 uc = *(const uint2*)(sAcc + r * SAW + lane * 4);
            float2 a0 = __half22float2(*(__half2*)&ua.x);
            float2 a1 = __half22float2(*(__half2*)&ua.y);
            float2 b0 = __half22float2(*(__half2*)&ub.x);
            float2 b1 = __half22float2(*(__half2*)&ub.y);
            float2 c0 = __half22float2(*(__half2*)&uc.x);
            float2 c1 = __half22float2(*(__half2*)&uc.y);
            float4 r4;
            r4.x = c0.x + a0.x + b0.x;
            r4.y = c0.y + a0.y + b0.y;
            r4.z = c1.x + a1.x + b1.x;
            r4.w = c1.y + a1.y + b1.y;
            *(float4*)(out + (size_t)e * 128 + lane * 4) = r4;
        }
        ga[i & 1] = nga;
        gb[i & 1] = ngb;
    }
}

// ---------------------------------------------------------------------------
extern "C" void kernel_launch(void* const* d_in, const int* in_sizes, int n_in,
                              void* d_out, int out_size) {
    const float* x  = (const float*)d_in[0];
    const int*   ei = (const int*)d_in[1];
    const float* ea = (const float*)d_in[2];
    const float* W  = (const float*)d_in[3];
    const float* b  = (const float*)d_in[4];
    float* out = (float*)d_out;

    const int gemm_smem = 2 * 128 * LDA * (int)sizeof(__half);     // 69632
    cudaFuncSetAttribute(gemm_mma,
                         cudaFuncAttributeMaxDynamicSharedMemorySize, gemm_smem);
    // sAcc 33792 + sEA 6144 + sWe 6144 + sIdx 1024 = 47104 B -> 4 blocks/SM
    const int edge_smem = (128 * SAW + 2 * 128 * EW) * 2 + 256 * 4;
    cudaFuncSetAttribute(edge_fused,
                         cudaFuncAttributeMaxDynamicSharedMemorySize, edge_smem);

    prep_Wt<<<128, 256>>>(W);
    prep_We<<<8, 256>>>(W);
    gemm_mma<<<dim3(2, (N_NODES + 127) / 128), 256, gemm_smem>>>(x, b);
    edge_fused<<<(N_EDGES + 127) / 128, 256, edge_smem>>>(ei, ea, out);
}